// round 2
// baseline (speedup 1.0000x reference)
#include <cuda_runtime.h>
#include <math.h>

#define T_LEN   3000
#define C_CH    1024
#define KSIZE   24
#define THREADS 256
#define ROUT    12          // outputs per thread; 250 active threads cover 3000
#define HALO    (KSIZE - 1) // 23
#define NPAIR   12          // weight pairs (w[2j], w[2j+1])

// Shared row buffer: [0..22] zero halo, [23..3022] data, pad so the last
// thread's float4 window reads (up to s[3023]) stay in bounds.
#define SBUF_LEN (HALO + T_LEN + 17)   // 3040 floats = 12160 B

// ---- packed f32x2 helpers (sm_103a FFMA2 path) ----
__device__ __forceinline__ unsigned long long pack_f32x2(float lo, float hi) {
    unsigned long long r;
    asm("mov.b64 %0, {%1, %2};" : "=l"(r) : "f"(lo), "f"(hi));
    return r;
}
__device__ __forceinline__ void ffma2(unsigned long long& acc,
                                      unsigned long long a,
                                      unsigned long long b) {
    asm("fma.rn.f32x2 %0, %1, %2, %0;" : "+l"(acc) : "l"(a), "l"(b));
}
__device__ __forceinline__ float reduce_f32x2(unsigned long long p) {
    float lo, hi;
    asm("mov.b64 {%0, %1}, %2;" : "=f"(lo), "=f"(hi) : "l"(p));
    return lo + hi;
}

__global__ __launch_bounds__(THREADS, 4)
void ssm4d_conv_kernel(const float* __restrict__ x,
                       const float* __restrict__ alpha,
                       const float* __restrict__ beta,
                       const float* __restrict__ theta,
                       float* __restrict__ y)
{
    __shared__ __align__(16) float s[SBUF_LEN];
    __shared__ __align__(8)  float wsh[KSIZE];

    const int row = blockIdx.x;            // row = b*C + c
    const int c   = row & (C_CH - 1);
    const float* __restrict__ xr = x + (size_t)row * T_LEN;
    float* __restrict__       yr = y + (size_t)row * T_LEN;
    const int tid = threadIdx.x;

    // Zero the causal halo and the tail pad.
    if (tid < HALO) s[tid] = 0.0f;
    if (tid >= HALO && tid < HALO + 17) s[T_LEN + tid] = 0.0f;

    // Synthesize the 24 depthwise taps for this channel (once per block).
    // w[k] = beta * exp(log(max(alpha,1e-6))*k) * (1 - (theta*k)^2/2 + (theta*k)^4/24)
    if (tid < KSIZE) {
        float a   = fmaxf(alpha[c], 1e-6f);
        float la  = logf(a);
        float k   = (float)tid;
        float dec = expf(la * k);
        float xx  = theta[c] * k;
        float x2  = xx * xx;
        float ph  = 1.0f - 0.5f * x2 + (x2 * x2) * (1.0f / 24.0f);
        wsh[tid]  = beta[c] * dec * ph;
    }

    // Stage the row into shared memory, coalesced.
    #pragma unroll
    for (int i = tid; i < T_LEN; i += THREADS)
        s[HALO + i] = xr[i];

    __syncthreads();

    if (tid < T_LEN / ROUT) {   // 250 active threads
        // Packed weights: W[j] = (w[2j], w[2j+1]).  12 x 64-bit = 24 regs.
        unsigned long long W[NPAIR];
        #pragma unroll
        for (int j = 0; j < NPAIR; j++) {
            float2 wv = *reinterpret_cast<const float2*>(&wsh[2 * j]);
            W[j] = pack_f32x2(wv.x, wv.y);
        }

        const int t0 = tid * ROUT;          // 48B-aligned window start
        const float* sp = &s[t0];

        // Packed accumulators: P[r] = (sum over even k, sum over odd k).
        unsigned long long P[ROUT];
        #pragma unroll
        for (int r = 0; r < ROUT; r++) P[r] = 0ull;

        // Stream the 35-float window as 9 float4 chunks with a 1-chunk
        // lookahead; build pairs (x[m], x[m+1]) for m = 0..33 and do
        //   P[r] += W[j] (*) (x[r+2j], x[r+2j+1])   with m = r + 2j.
        // 144 FFMA2 total (vs 288 FFMA before).
        float4 q = *reinterpret_cast<const float4*>(sp);
        #pragma unroll
        for (int cch = 0; cch < 9; cch++) {
            float4 qn = (cch < 8)
                ? *reinterpret_cast<const float4*>(sp + 4 * cch + 4)
                : make_float4(0.f, 0.f, 0.f, 0.f);
            float f0 = q.x, f1 = q.y, f2 = q.z, f3 = q.w, f4 = qn.x;
            #pragma unroll
            for (int i = 0; i < 4; i++) {
                const int m = 4 * cch + i;   // pair base index, need m <= 33
                if (m > 33) break;
                float lo = (i == 0) ? f0 : (i == 1) ? f1 : (i == 2) ? f2 : f3;
                float hi = (i == 0) ? f1 : (i == 1) ? f2 : (i == 2) ? f3 : f4;
                unsigned long long xp = pack_f32x2(lo, hi);
                #pragma unroll
                for (int j = 0; j < NPAIR; j++) {
                    const int r = m - 2 * j;
                    if (0 <= r && r < ROUT)
                        ffma2(P[r], W[j], xp);
                }
            }
            q = qn;
        }

        // Reduce packed (even,odd) partials and store: 3x STG.128 per thread.
        #pragma unroll
        for (int r = 0; r < ROUT; r += 4) {
            float4 v = make_float4(reduce_f32x2(P[r]),
                                   reduce_f32x2(P[r + 1]),
                                   reduce_f32x2(P[r + 2]),
                                   reduce_f32x2(P[r + 3]));
            *reinterpret_cast<float4*>(&yr[t0 + r]) = v;
        }
    }
}

extern "C" void kernel_launch(void* const* d_in, const int* in_sizes, int n_in,
                              void* d_out, int out_size)
{
    const float* x     = (const float*)d_in[0];
    const float* alpha = (const float*)d_in[1];
    const float* beta  = (const float*)d_in[2];
    const float* theta = (const float*)d_in[3];
    float* y = (float*)d_out;

    const int rows = in_sizes[0] / T_LEN;   // B*C = 16384
    ssm4d_conv_kernel<<<rows, THREADS>>>(x, alpha, beta, theta, y);
}

// round 3
// speedup vs baseline: 1.0090x; 1.0090x over previous
#include <cuda_runtime.h>
#include <math.h>

#define T_LEN   3000
#define C_CH    1024
#define KSIZE   24
#define THREADS 256
#define ROUT    12          // outputs per thread; 250 active threads cover 3000
#define HALO    (KSIZE - 1) // 23
#define NPAIR   12          // weight pairs (w[2j], w[2j+1])

// Shared row buffer: [0..22] zero halo, [23..3022] data, pad so the last
// thread's 128-bit window loads (up to s[3023]) stay in bounds.
#define SBUF_LEN (HALO + T_LEN + 17)   // 3040 floats = 12160 B

typedef unsigned long long u64;

// fma.rn.f32x2: packed dual-FMA (SASS FFMA2) — sm_103a only via PTX.
__device__ __forceinline__ void ffma2(u64& acc, u64 a, u64 b) {
    asm("fma.rn.f32x2 %0, %1, %2, %0;" : "+l"(acc) : "l"(a), "l"(b));
}
// (hi(a), lo(b)) — odd-aligned pair from two even-aligned pairs.
__device__ __forceinline__ u64 crosspair(u64 a, u64 b) {
    u64 r;
    asm("{\n\t"
        ".reg .b32 al, ah, bl, bh;\n\t"
        "mov.b64 {al, ah}, %1;\n\t"
        "mov.b64 {bl, bh}, %2;\n\t"
        "mov.b64 %0, {ah, bl};\n\t"
        "}" : "=l"(r) : "l"(a), "l"(b));
    return r;
}
__device__ __forceinline__ float reduce_f32x2(u64 p) {
    float lo, hi;
    asm("mov.b64 {%0, %1}, %2;" : "=f"(lo), "=f"(hi) : "l"(p));
    return lo + hi;
}

__global__ __launch_bounds__(THREADS, 3)
void ssm4d_conv_kernel(const float* __restrict__ x,
                       const float* __restrict__ alpha,
                       const float* __restrict__ beta,
                       const float* __restrict__ theta,
                       float* __restrict__ y)
{
    __shared__ __align__(16) float s[SBUF_LEN];
    __shared__ __align__(8)  float wsh[KSIZE];

    const int row = blockIdx.x;            // row = b*C + c
    const int c   = row & (C_CH - 1);
    const float* __restrict__ xr = x + (size_t)row * T_LEN;
    float* __restrict__       yr = y + (size_t)row * T_LEN;
    const int tid = threadIdx.x;

    // Zero the causal halo and the tail pad.
    if (tid < HALO) s[tid] = 0.0f;
    if (tid >= HALO && tid < HALO + 17) s[T_LEN + tid] = 0.0f;

    // Synthesize the 24 depthwise taps for this channel (once per block).
    // w[k] = beta * exp(log(max(alpha,1e-6))*k) * (1 - (theta*k)^2/2 + (theta*k)^4/24)
    if (tid < KSIZE) {
        float a   = fmaxf(alpha[c], 1e-6f);
        float la  = logf(a);
        float k   = (float)tid;
        float dec = expf(la * k);
        float xx  = theta[c] * k;
        float x2  = xx * xx;
        float ph  = 1.0f - 0.5f * x2 + (x2 * x2) * (1.0f / 24.0f);
        wsh[tid]  = beta[c] * dec * ph;
    }

    // Stage the row into shared memory, coalesced.
    #pragma unroll
    for (int i = tid; i < T_LEN; i += THREADS)
        s[HALO + i] = xr[i];

    __syncthreads();

    if (tid < T_LEN / ROUT) {   // 250 active threads
        // Weight pairs straight from smem as aligned 64-bit loads (LDS.64,
        // broadcast, zero packing MOVs).
        u64 W[NPAIR];
        #pragma unroll
        for (int j = 0; j < NPAIR; j++)
            W[j] = *reinterpret_cast<const u64*>(&wsh[2 * j]);

        const int t0 = tid * ROUT;          // 48B-aligned window start
        const float* sp = &s[t0];

        // Packed accumulators: P[r] holds (even-tap partial, odd-tap partial)
        // of output r.
        u64 P[ROUT];
        #pragma unroll
        for (int r = 0; r < ROUT; r++) P[r] = 0ull;

        // Pair-major streaming over the 36-float window:
        //   E[p]   = (s[t0+2p],   s[t0+2p+1])   p = 0..17  (even-aligned, free)
        //   O[p]   = (s[t0+2p+1], s[t0+2p+2])   p = 0..16  (crosspair)
        //   even r: P[r] += W[j] (*) E[r/2 + j]
        //   odd  r: P[r] += W[j] (*) O[(r-1)/2 + j]
        u64 Eprev1 = 0ull;   // E[2q-1] from the previous iteration
        #pragma unroll
        for (int q = 0; q < 9; q++) {
            ulonglong2 v = *reinterpret_cast<const ulonglong2*>(sp + 4 * q);
            const u64 E0 = v.x;   // E[2q]
            const u64 E1 = v.y;   // E[2q+1]

            // Even pairs feed even outputs r = 2*(e - j).
            #pragma unroll
            for (int j = 0; j < NPAIR; j++) {
                { const int r = 2 * (2 * q - j);
                  if (0 <= r && r <= 10) ffma2(P[r], W[j], E0); }
                { const int r = 2 * (2 * q + 1 - j);
                  if (0 <= r && r <= 10) ffma2(P[r], W[j], E1); }
            }

            // Odd pairs: O[2q-1] = (hi E[2q-1], lo E[2q]),
            //            O[2q]   = (hi E[2q],   lo E[2q+1]).
            if (q > 0) {
                const u64 Oa = crosspair(Eprev1, E0);   // O[2q-1]
                #pragma unroll
                for (int j = 0; j < NPAIR; j++) {
                    const int r = 2 * (2 * q - 1 - j) + 1;
                    if (1 <= r && r <= 11) ffma2(P[r], W[j], Oa);
                }
            }
            {
                const u64 Ob = crosspair(E0, E1);       // O[2q]
                #pragma unroll
                for (int j = 0; j < NPAIR; j++) {
                    const int r = 2 * (2 * q - j) + 1;
                    if (1 <= r && r <= 11) ffma2(P[r], W[j], Ob);
                }
            }
            Eprev1 = E1;
        }

        // Reduce (even,odd) partials and store: 3x STG.128 per thread.
        #pragma unroll
        for (int r = 0; r < ROUT; r += 4) {
            float4 o = make_float4(reduce_f32x2(P[r]),
                                   reduce_f32x2(P[r + 1]),
                                   reduce_f32x2(P[r + 2]),
                                   reduce_f32x2(P[r + 3]));
            *reinterpret_cast<float4*>(&yr[t0 + r]) = o;
        }
    }
}

extern "C" void kernel_launch(void* const* d_in, const int* in_sizes, int n_in,
                              void* d_out, int out_size)
{
    const float* x     = (const float*)d_in[0];
    const float* alpha = (const float*)d_in[1];
    const float* beta  = (const float*)d_in[2];
    const float* theta = (const float*)d_in[3];
    float* y = (float*)d_out;

    const int rows = in_sizes[0] / T_LEN;   // B*C = 16384
    ssm4d_conv_kernel<<<rows, THREADS>>>(x, alpha, beta, theta, y);
}

// round 4
// speedup vs baseline: 1.1821x; 1.1715x over previous
#include <cuda_runtime.h>
#include <math.h>

#define T_LEN    3000
#define C_CH     1024
#define KSIZE    24
#define HALO     (KSIZE - 1)   // 23
#define SEG      1500          // outputs per CTA (half a row)
#define THREADS  128
#define NGROUP   (SEG / 4)     // 375 groups of 4 consecutive outputs

// s[i] = x_seg[i - 23]; outputs j use s[j..j+23]; group g reads s[4g..4g+27]
// (7x LDS.128 reads 28 floats). Max touched: s[4*374+27] = s[1523]. Pad to 1536.
#define SBUF_LEN 1536          // 6144 B

__global__ __launch_bounds__(THREADS, 8)
void ssm4d_conv_kernel(const float* __restrict__ x,
                       const float* __restrict__ alpha,
                       const float* __restrict__ beta,
                       const float* __restrict__ theta,
                       float* __restrict__ y)
{
    __shared__ __align__(16) float s[SBUF_LEN];
    __shared__ float wsh[KSIZE];

    const int row  = blockIdx.x >> 1;        // row = b*C + c
    const int half = blockIdx.x & 1;
    const int c    = row & (C_CH - 1);
    const int tid  = threadIdx.x;

    const float* __restrict__ xseg = x + (size_t)row * T_LEN + half * SEG;
    float* __restrict__       yseg = y + (size_t)row * T_LEN + half * SEG;

    // Halo: first half of the row gets zeros; second half gets real data.
    if (tid < HALO)
        s[tid] = half ? xseg[tid - HALO] : 0.0f;
    // Tail pad s[1523..1535] (one element is over-read by the last group).
    if (tid >= HALO && tid < HALO + 13)
        s[SEG + tid] = 0.0f;

    // Synthesize the 24 depthwise taps for this channel (once per block).
    // w[k] = beta * exp(log(max(alpha,1e-6))*k) * (1 - (theta*k)^2/2 + (theta*k)^4/24)
    if (tid < KSIZE) {
        float a   = fmaxf(alpha[c], 1e-6f);
        float la  = logf(a);
        float k   = (float)tid;
        float dec = expf(la * k);
        float xx  = theta[c] * k;
        float x2  = xx * xx;
        float ph  = 1.0f - 0.5f * x2 + (x2 * x2) * (1.0f / 24.0f);
        wsh[tid]  = beta[c] * dec * ph;
    }

    // Stage the segment, coalesced & aligned.
    #pragma unroll
    for (int i = tid; i < SEG; i += THREADS)
        s[HALO + i] = xseg[i];

    __syncthreads();

    // Weights to registers (LDS broadcast, conflict-free).
    float w[KSIZE];
    #pragma unroll
    for (int k = 0; k < KSIZE; k++) w[k] = wsh[k];

    // Each thread handles groups g = tid, tid+128, tid+256 (g < 375).
    // Group g = 4 consecutive outputs [4g..4g+3]; lanes are 16B apart ->
    // every LDS.128 below is a contiguous 512B warp access (conflict-free),
    // and every STG.128 is a perfectly coalesced 512B warp store.
    #pragma unroll
    for (int gi = 0; gi < 3; gi++) {
        const int g = tid + gi * THREADS;
        if (g < NGROUP) {
            const float* sp = &s[4 * g];

            float xw[28];
            #pragma unroll
            for (int q = 0; q < 7; q++) {
                float4 v = *reinterpret_cast<const float4*>(sp + 4 * q);
                xw[4*q]   = v.x; xw[4*q+1] = v.y;
                xw[4*q+2] = v.z; xw[4*q+3] = v.w;
            }

            float a0 = 0.f, a1 = 0.f, a2 = 0.f, a3 = 0.f;
            #pragma unroll
            for (int k = 0; k < KSIZE; k++) {
                a0 = fmaf(w[k], xw[k    ], a0);
                a1 = fmaf(w[k], xw[k + 1], a1);
                a2 = fmaf(w[k], xw[k + 2], a2);
                a3 = fmaf(w[k], xw[k + 3], a3);
            }

            *reinterpret_cast<float4*>(&yseg[4 * g]) =
                make_float4(a0, a1, a2, a3);
        }
    }
}

extern "C" void kernel_launch(void* const* d_in, const int* in_sizes, int n_in,
                              void* d_out, int out_size)
{
    const float* x     = (const float*)d_in[0];
    const float* alpha = (const float*)d_in[1];
    const float* beta  = (const float*)d_in[2];
    const float* theta = (const float*)d_in[3];
    float* y = (float*)d_out;

    const int rows = in_sizes[0] / T_LEN;   // B*C = 16384
    ssm4d_conv_kernel<<<rows * 2, THREADS>>>(x, alpha, beta, theta, y);
}